// round 16
// baseline (speedup 1.0000x reference)
#include <cuda_runtime.h>
#include <cuda_bf16.h>

#define NN   10000
#define OO   16
#define CC   64
#define EE   100000
#define KDD  64
#define NOC  (NN*OO*CC)          // 10,240,000
#define TILE (OO*CC)             // 1024 elements per node/edge tile
#define NGRP (NN/8)              // 1250 groups of 8 nodes

// column permutation applied to g_x1 / g_xb tiles (element index within a 64-elem row)
// (row&7)<<3: 32-bank-conflict-free fragment access in k_edge msg hmul, while
// preserving 8-element (16B) block alignment for vector ld/st.
#define PERM(row, col) ((col) ^ (((row) & 7) << 3))

// -------- device scratch (no allocations allowed) --------
__device__ __align__(16) __nv_bfloat16  g_x1[NOC];      // 20.5 MB spatial-conv accumulator (bf16, PERMuted)
__device__ __align__(16) __nv_bfloat16  g_xb[NOC];      // 20.5 MB bf16 permuted copy of x
__device__ __align__(16) __nv_bfloat162 g_fkb[8192];    // fiber kernel bf16 (pre /O)
__device__ __align__(16) unsigned       g_kwp[2048];    // kernel_w  B-frags (4kt x 8nt)
__device__ __align__(16) unsigned       g_w1p[8192];    // w1 B-frags (4kt x 32nt)
__device__ __align__(16) unsigned       g_w2p[8192];    // w2 B-frags (16kt x 8nt)

// -------- helpers --------
__device__ __forceinline__ unsigned pk(float lo, float hi) {
    __nv_bfloat162 t = __floats2bfloat162_rn(lo, hi);   // .x = lo (low 16 bits)
    return *reinterpret_cast<unsigned*>(&t);
}

__device__ __forceinline__ void mma_bf16(float* c, const unsigned* a, unsigned b0, unsigned b1) {
    asm volatile(
        "mma.sync.aligned.m16n8k16.row.col.f32.bf16.bf16.f32 "
        "{%0,%1,%2,%3}, {%4,%5,%6,%7}, {%8,%9}, {%0,%1,%2,%3};"
        : "+f"(c[0]), "+f"(c[1]), "+f"(c[2]), "+f"(c[3])
        : "r"(a[0]), "r"(a[1]), "r"(a[2]), "r"(a[3]), "r"(b0), "r"(b1));
}

__device__ __forceinline__ void mbar_wait(unsigned mbar, int phase) {
    asm volatile(
        "{\n\t.reg .pred P1;\n\t"
        "WAIT_LOOP_%=:\n\t"
        "mbarrier.try_wait.parity.acquire.cta.shared::cta.b64 P1, [%0], %1, 0x989680;\n\t"
        "@P1 bra.uni WAIT_DONE_%=;\n\t"
        "bra.uni WAIT_LOOP_%=;\n\t"
        "WAIT_DONE_%=:\n\t}"
        :: "r"(mbar), "r"(phase) : "memory");
}

// =========================================================
// K0: fused prep — zero g_x1 AND build g_xb (bf16 permuted x) in one pass
// =========================================================
__global__ void k_prep0(const float* __restrict__ x) {
    const int n4 = NOC / 4;          // 2,560,000 float4s
    int i = blockIdx.x * blockDim.x + threadIdx.x;
    const int stride = gridDim.x * blockDim.x;
    const uint2 z = make_uint2(0u, 0u);
    for (; i < n4; i += stride) {
        float4 v = ((const float4*)x)[i];
        const int node = i >> 8;
        const int f    = (i & 255) * 4;      // element index within tile
        const int row  = f >> 6, col = f & 63;
        const int pc   = PERM(row, col);
        uint2 o;
        o.x = pk(v.x, v.y);
        o.y = pk(v.z, v.w);
        *(uint2*)(g_xb + (size_t)node * 1024 + row * 64 + pc) = o;
        *(uint2*)(g_x1 + (size_t)node * 1024 + row * 64 + pc) = z;
    }
}

// =========================================================
// K1: fk[p][o][c] = (1/O) * sum_kd FKB[p,o,kd] * FW[kd,c]  -> bf16 pairs
// =========================================================
__global__ void k_fk(const float* __restrict__ fkb, const float* __restrict__ fw) {
    __shared__ float s[KDD];
    const int po = blockIdx.x;
    const int t  = threadIdx.x;
    s[t]      = fkb[po * KDD + t];
    s[t + 32] = fkb[po * KDD + t + 32];
    __syncthreads();
    float a0 = 0.f, a1 = 0.f;
#pragma unroll 16
    for (int kd = 0; kd < KDD; kd++) {
        a0 += s[kd] * fw[kd * CC + 2 * t];
        a1 += s[kd] * fw[kd * CC + 2 * t + 1];
    }
    g_fkb[po * 32 + t] = __floats2bfloat162_rn(a0 * (1.0f / OO), a1 * (1.0f / OO));
}

// =========================================================
// K1b: pack kernel_w / w1 / w2 into mma B-fragment layout (bf16)
// Parallelized over 16 blocks x 8 warps = 128 warp-slots.
// =========================================================
__global__ void k_pack(const float* __restrict__ kw,
                       const float* __restrict__ w1,
                       const float* __restrict__ w2) {
    const int tid  = threadIdx.x;
    const int wrp  = tid >> 5, lane = tid & 31;
    const int g    = lane >> 2, tg = lane & 3;
    const int slot = blockIdx.x * 8 + wrp;      // 0..127
    for (int f = slot; f < 32; f += 128) {
        const int kt = f >> 3, nt = f & 7;
        const int k = kt * 16 + 2 * tg, n = nt * 8 + g;
        g_kwp[(f * 32 + lane) * 2 + 0] = pk(kw[k * 64 + n],       kw[(k + 1) * 64 + n]);
        g_kwp[(f * 32 + lane) * 2 + 1] = pk(kw[(k + 8) * 64 + n], kw[(k + 9) * 64 + n]);
    }
    for (int f = slot; f < 128; f += 128) {
        const int kt = f >> 5, nt = f & 31;
        const int k = kt * 16 + 2 * tg, n = nt * 8 + g;
        g_w1p[(f * 32 + lane) * 2 + 0] = pk(w1[k * 256 + n],       w1[(k + 1) * 256 + n]);
        g_w1p[(f * 32 + lane) * 2 + 1] = pk(w1[(k + 8) * 256 + n], w1[(k + 9) * 256 + n]);
    }
    for (int f = slot; f < 128; f += 128) {
        const int kt = f >> 3, nt = f & 7;
        const int k = kt * 16 + 2 * tg, n = nt * 8 + g;
        g_w2p[(f * 32 + lane) * 2 + 0] = pk(w2[k * 64 + n],       w2[(k + 1) * 64 + n]);
        g_w2p[(f * 32 + lane) * 2 + 1] = pk(w2[(k + 8) * 64 + n], w2[(k + 9) * 64 + n]);
    }
}

// =========================================================
// K2: edge conv. kb streamed with L2::evict_first; x from bf16 g_xb;
// msg built in-place in a double-buffered bf16 scatter buffer
// (conflict-free fragment access via widened PERM).
// 8 warps/block, 4 edges/warp, grid=3125.
// smem: Wp 8KB + KBS 16KB + XB 32KB = 56KB, target 4 blocks/SM (64 regs).
// =========================================================
__global__ void __launch_bounds__(256, 4) k_edge(
    const float* __restrict__ kb,
    const int*   __restrict__ ei)
{
    extern __shared__ float sme[];
    unsigned* Wp      = (unsigned*)sme;             // 2048 u32  (8KB)
    unsigned* KBS_all = Wp + 2048;                  // 4096 u32  (16KB) bf16 kb tiles
    unsigned* XB_all  = KBS_all + 4096;             // 8 warps x 2 x 512 u32 (32KB)

    const int tid  = threadIdx.x;
    const int wrp  = tid >> 5, lane = tid & 31;
    const int g    = lane >> 2, tg = lane & 3;

    for (int i = tid; i < 2048; i += 256) Wp[i] = g_kwp[i];
    __syncthreads();

    char*     KBS = (char*)(KBS_all + wrp * 512);   // 2KB bf16 tile, swizzled
    unsigned* XB  = XB_all + wrp * 1024;            // 2 x 2KB bf16 msg buffers

    // L2 eviction policy: kb is streamed once, keep xb/x1 resident
    unsigned long long pol;
    asm volatile("createpolicy.fractional.L2::evict_first.b64 %0, 1.0;" : "=l"(pol));

    const int lrow  = lane & 15;
    const int lhalf = lane >> 4;
    const unsigned kbs_base = (unsigned)__cvta_generic_to_shared(KBS);

#pragma unroll 1
    for (int it = 0; it < 4; ++it) {
        const int e   = blockIdx.x * 32 + wrp * 4 + it;
        const int src = ei[e];
        const int dst = ei[EE + e];

        const int buf = it & 1;
        unsigned* mb = XB + buf * 512;
        // drain scatter that used this buffer (issued 2 iterations ago)
        if (lane == 0 && it >= 2)
            asm volatile("cp.async.bulk.wait_group 1;" ::: "memory");
        __syncwarp();

        // ---- kb -> bf16 swizzled smem, 2 chunks of 4 float4 ----
        const float4* kb4 = (const float4*)(kb + (size_t)e * TILE);
#pragma unroll
        for (int ch = 0; ch < 2; ++ch) {
            float4 kv[4];
#pragma unroll
            for (int i = 0; i < 4; ++i)
                asm volatile("ld.global.nc.L2::cache_hint.v4.f32 {%0,%1,%2,%3}, [%4], %5;"
                             : "=f"(kv[i].x), "=f"(kv[i].y), "=f"(kv[i].z), "=f"(kv[i].w)
                             : "l"(kb4 + (ch * 4 + i) * 32 + lane), "l"(pol));
#pragma unroll
            for (int i = 0; i < 4; ++i) {
                const int idx = (ch * 4 + i) * 32 + lane;   // float4 index in tile
                const int row = idx >> 4;                   // 0..15
                const int bc  = (idx & 15) * 8;             // byte col (0..120)
                const int bcs = bc ^ ((row & 7) << 4);      // SW128 swizzle
                uint2 v;
                v.x = pk(kv[i].x, kv[i].y);
                v.y = pk(kv[i].z, kv[i].w);
                *(uint2*)(KBS + row * 128 + bcs) = v;
            }
        }

        // ---- xb (already permuted bf16) -> msg buffer, 2 chunks of 2 uint4 ----
        const uint4* xb4 = (const uint4*)(g_xb + (size_t)src * TILE);
#pragma unroll
        for (int ch = 0; ch < 2; ++ch) {
            uint4 xv[2];
#pragma unroll
            for (int i = 0; i < 2; ++i) xv[i] = xb4[(ch * 2 + i) * 32 + lane];
#pragma unroll
            for (int i = 0; i < 2; ++i) ((uint4*)mb)[(ch * 2 + i) * 32 + lane] = xv[i];
        }
        __syncwarp();   // KBS + mb staging visible warp-wide

        // ---- A fragments via ldmatrix ----
        unsigned A[4][4];
#pragma unroll
        for (int kt = 0; kt < 4; ++kt) {
            const int bc  = kt * 32 + lhalf * 16;
            const unsigned addr = kbs_base + lrow * 128 + (bc ^ ((lrow & 7) << 4));
            asm volatile(
                "ldmatrix.sync.aligned.m8n8.x4.shared.b16 {%0,%1,%2,%3}, [%4];"
                : "=r"(A[kt][0]), "=r"(A[kt][1]), "=r"(A[kt][2]), "=r"(A[kt][3])
                : "r"(addr));
        }

        // ---- 2 passes of 4 n-tiles: mma then in-place msg hmul ----
#pragma unroll 1
        for (int pass = 0; pass < 2; ++pass) {
            float c[4][4];
#pragma unroll
            for (int ntl = 0; ntl < 4; ++ntl)
                c[ntl][0] = c[ntl][1] = c[ntl][2] = c[ntl][3] = 0.f;
#pragma unroll
            for (int kt = 0; kt < 4; ++kt)
#pragma unroll
                for (int ntl = 0; ntl < 4; ++ntl) {
                    const int nt = pass * 4 + ntl;
                    uint2 b = *(const uint2*)&Wp[((kt * 8 + nt) * 32 + lane) * 2];
                    mma_bf16(c[ntl], A[kt], b.x, b.y);
                }
#pragma unroll
            for (int ntl = 0; ntl < 4; ++ntl) {
                const int nt = pass * 4 + ntl;
                const int c0 = nt * 8 + 2 * tg;
                const int w  = PERM(g, c0) >> 1;    // bf162 word col (same for g, g+8)
                unsigned x0 = mb[g * 32 + w];
                unsigned x1 = mb[(g + 8) * 32 + w];
                unsigned k0 = pk(c[ntl][0], c[ntl][1]);
                unsigned k1 = pk(c[ntl][2], c[ntl][3]);
                __nv_bfloat162 m0 = __hmul2(*(__nv_bfloat162*)&x0, *(__nv_bfloat162*)&k0);
                __nv_bfloat162 m1 = __hmul2(*(__nv_bfloat162*)&x1, *(__nv_bfloat162*)&k1);
                mb[g * 32 + w]       = *(unsigned*)&m0;
                mb[(g + 8) * 32 + w] = *(unsigned*)&m1;
            }
        }
        __syncwarp();

        if (lane == 0) {
            asm volatile("fence.proxy.async.shared::cta;" ::: "memory");
            unsigned saddr = (unsigned)__cvta_generic_to_shared(mb);
            char* gptr = (char*)g_x1 + (size_t)dst * 2048;
            asm volatile(
                "cp.reduce.async.bulk.global.shared::cta.bulk_group.add.noftz.bf16 [%0], [%1], %2;"
                :: "l"(gptr), "r"(saddr), "r"(2048) : "memory");
            asm volatile("cp.async.bulk.commit_group;" ::: "memory");
        }
    }
    if (lane == 0)
        asm volatile("cp.async.bulk.wait_group 0;" ::: "memory");
    __syncwarp();
}

// =========================================================
// K3: persistent fused fiber conv + LN + bf16-MMA MLP + residual
// grid=148, 512 threads. x1 tiles prefetched via cp.async.bulk (double buffer),
// fk in registers, per-node-pair named barrier between MLP1/MLP2,
// epilogue staged through x2 smem for fully coalesced residual+store.
// =========================================================
#define X2S 68                                 // x2 row stride (float4-aligned)
#define FUSE_SMEM_FLOATS (8192*2 + 128*X2S + 128 + 128 + 256 + 64*5 + 4 + 16896 + 8192)
#define FUSE_SMEM_BYTES  (FUSE_SMEM_FLOATS * 4)

__global__ void __launch_bounds__(512, 1) k_fuse(
    const float* __restrict__ x,
    const float* __restrict__ cb,
    const float* __restrict__ lns,
    const float* __restrict__ lnb,
    const float* __restrict__ b1,
    const float* __restrict__ b2,
    const float* __restrict__ ls,
    float*       __restrict__ out)
{
    extern __shared__ float sm[];
    unsigned* w1p  = (unsigned*)sm;                    // 8192 u32 (32KB)
    unsigned* w2p  = w1p + 8192;                       // 8192 u32 (32KB)
    float* x2    = (float*)(w2p + 8192);               // 128 x 68 f32 (34.8KB)
    float* mu_s  = x2 + 128 * X2S;                     // 128
    float* rs_s  = mu_s + 128;                         // 128
    float* b1_s  = rs_s + 128;                         // 256
    float* b2_s  = b1_s + 256;                         // 64
    float* ls_s  = b2_s + 64;                          // 64
    float* lns_s = ls_s + 64;                          // 64
    float* lnb_s = lns_s + 64;                         // 64
    float* cb_s  = lnb_s + 64;                         // 64
    unsigned long long* mbar = (unsigned long long*)(cb_s + 64);  // 2 mbarriers (16B)
    unsigned* h1 = (unsigned*)(mbar + 2);              // 128 x 132 u32 (66KB)
    __nv_bfloat16* stage = (__nv_bfloat16*)(h1 + 16896); // 2 x 8192 bf16 (32KB)

    const int tid  = threadIdx.x;
    const int wrp  = tid >> 5, lane = tid & 31;
    const int g    = lane >> 2, tg = lane & 3;
    const int nloc = wrp >> 1;        // 0..7: node within group
    const int sub  = wrp & 1;         // warp's half of the MLP

    const unsigned mb0 = (unsigned)__cvta_generic_to_shared(&mbar[0]);
    const unsigned mb1 = (unsigned)__cvta_generic_to_shared(&mbar[1]);

    for (int i = tid; i < 8192; i += 512) {
        w1p[i] = g_w1p[i];
        w2p[i] = g_w2p[i];
    }
    if (tid < 64) {
        b2_s[tid]  = b2[tid];
        ls_s[tid]  = ls[tid] * 1e-6f;   // fold LS_VAL
        lns_s[tid] = lns[tid];
        lnb_s[tid] = lnb[tid];
        cb_s[tid]  = cb[tid];
    }
    if (tid < 256) b1_s[tid] = b1[tid];
    if (tid == 0) {
        asm volatile("mbarrier.init.shared.b64 [%0], 1;" :: "r"(mb0) : "memory");
        asm volatile("mbarrier.init.shared.b64 [%0], 1;" :: "r"(mb1) : "memory");
    }

    // ---- hoist fiber kernel into registers: thread = (c4, p, half) ----
    const int c4 = tid & 15, fp_ = (tid >> 4) & 15, half = tid >> 8;
    __nv_bfloat162 fkr0[16], fkr1[16];
#pragma unroll
    for (int o = 0; o < 16; ++o) {
        uint2 v = *(const uint2*)&((const unsigned*)g_fkb)[fp_ * 512 + o * 32 + 2 * c4];
        fkr0[o] = *reinterpret_cast<__nv_bfloat162*>(&v.x);
        fkr1[o] = *reinterpret_cast<__nv_bfloat162*>(&v.y);
    }
    __syncthreads();
    const float4 cbv = *(const float4*)&cb_s[4 * c4];

    // ---- prologue: prefetch first group's x1 tile into stage buf 0 ----
    if (tid == 0) {
        asm volatile("mbarrier.arrive.expect_tx.shared.b64 _, [%0], 16384;" :: "r"(mb0) : "memory");
        unsigned sdst = (unsigned)__cvta_generic_to_shared(stage);
        const char* gsrc = (const char*)g_x1 + (size_t)blockIdx.x * 16384;
        asm volatile(
            "cp.async.bulk.shared::cta.global.mbarrier::complete_tx::bytes [%0], [%1], 16384, [%2];"
            :: "r"(sdst), "l"(gsrc), "r"(mb0) : "memory");
    }

    int ph0 = 0, ph1 = 0;
    int it = 0;
#pragma unroll 1
    for (int grp = blockIdx.x; grp < NGRP; grp += 148, ++it) {
        const int nodebase = grp * 8;
        const int buf = it & 1;
        const __nv_bfloat16* stg = stage + buf * 8192;

        // ---- wait for this group's x1 tile ----
        if (buf == 0) { mbar_wait(mb0, ph0); ph0 ^= 1; }
        else          { mbar_wait(mb1, ph1); ph1 ^= 1; }

        // ---- fiber conv (bf162 hfma2, fk in regs): 4 nodes per thread ----
#pragma unroll
        for (int n = 0; n < 4; ++n) {
            const int node = half * 4 + n;
            const __nv_bfloat16* sp = stg + node * 1024;
            __nv_bfloat162 acc0 = __floats2bfloat162_rn(0.f, 0.f);
            __nv_bfloat162 acc1 = acc0;
#pragma unroll
            for (int o = 0; o < 16; ++o) {
                uint2 xv = *(const uint2*)(sp + o * 64 + PERM(o, 4 * c4));
                acc0 = __hfma2(*reinterpret_cast<__nv_bfloat162*>(&xv.x), fkr0[o], acc0);
                acc1 = __hfma2(*reinterpret_cast<__nv_bfloat162*>(&xv.y), fkr1[o], acc1);
            }
            float2 a0 = __bfloat1622float2(acc0);
            float2 a1 = __bfloat1622float2(acc1);
            *(float4*)&x2[(node * 16 + fp_) * X2S + 4 * c4] =
                make_float4(a0.x + cbv.x, a0.y + cbv.y, a1.x + cbv.z, a1.y + cbv.w);
        }
        __syncthreads();   // x2 ready; everyone done reading stage[buf]

        // ---- prefetch next group's x1 into the other buffer ----
        if (tid == 0 && grp + 148 < NGRP) {
            const unsigned mbn = (buf == 0) ? mb1 : mb0;
            asm volatile("mbarrier.arrive.expect_tx.shared.b64 _, [%0], 16384;" :: "r"(mbn) : "memory");
            unsigned sdst = (unsigned)__cvta_generic_to_shared(stage + (buf ^ 1) * 8192);
            const char* gsrc = (const char*)g_x1 + (size_t)(grp + 148) * 16384;
            asm volatile(
                "cp.async.bulk.shared::cta.global.mbarrier::complete_tx::bytes [%0], [%1], 16384, [%2];"
                :: "r"(sdst), "l"(gsrc), "r"(mbn) : "memory");
        }

        // ---- LayerNorm stats: 4 threads per row (float4, aligned via X2S=68) ----
        {
            const int row = tid >> 2, q = tid & 3;
            const float* xr = x2 + row * X2S + q * 16;
            float s = 0.f, ss = 0.f;
#pragma unroll
            for (int j = 0; j < 4; ++j) {
                float4 v = *(const float4*)(xr + j * 4);
                s  += v.x + v.y + v.z + v.w;
                ss += v.x * v.x + v.y * v.y + v.z * v.z + v.w * v.w;
            }
            s  += __shfl_xor_sync(0xffffffffu, s, 1);
            ss += __shfl_xor_sync(0xffffffffu, ss, 1);
            s  += __shfl_xor_sync(0xffffffffu, s, 2);
            ss += __shfl_xor_sync(0xffffffffu, ss, 2);
            if (q == 0) {
                const float mu  = s * (1.f / 64.f);
                const float var = ss * (1.f / 64.f) - mu * mu;
                mu_s[row] = mu;
                rs_s[row] = rsqrtf(var + 1e-6f);
            }
        }
        __syncthreads();

        // ---- build normalized A fragments ----
        const int r0  = nloc * 16 + g;
        const float mu0 = mu_s[r0],     rs0 = rs_s[r0];
        const float mu1 = mu_s[r0 + 8], rs1 = rs_s[r0 + 8];
        unsigned A[4][4];
#pragma unroll
        for (int kt = 0; kt < 4; ++kt) {
            const int k0 = kt * 16 + 2 * tg;
            float2 sc0 = *(float2*)(lns_s + k0),     bi0 = *(float2*)(lnb_s + k0);
            float2 sc1 = *(float2*)(lns_s + k0 + 8), bi1 = *(float2*)(lnb_s + k0 + 8);
            float2 v;
            v = *(float2*)(x2 + r0 * X2S + k0);
            A[kt][0] = pk((v.x - mu0) * rs0 * sc0.x + bi0.x, (v.y - mu0) * rs0 * sc0.y + bi0.y);
            v = *(float2*)(x2 + (r0 + 8) * X2S + k0);
            A[kt][1] = pk((v.x - mu1) * rs1 * sc0.x + bi0.x, (v.y - mu1) * rs1 * sc0.y + bi0.y);
            v = *(float2*)(x2 + r0 * X2S + k0 + 8);
            A[kt][2] = pk((v.x - mu0) * rs0 * sc1.x + bi1.x, (v.y - mu0) * rs0 * sc1.y + bi1.y);
            v = *(float2*)(x2 + (r0 + 8) * X2S + k0 + 8);
            A[kt][3] = pk((v.x - mu1) * rs1 * sc1.x + bi1.x, (v.y - mu1) * rs1 * sc1.y + bi1.y);
        }

        // ---- MLP1: this warp's half (16 of 32 n-tiles) ----
        {
            float c1r[16][4];
#pragma unroll
            for (int nt = 0; nt < 16; ++nt) {
                const int col = (sub * 16 + nt) * 8 + 2 * tg;
                c1r[nt][0] = b1_s[col]; c1r[nt][1] = b1_s[col + 1];
                c1r[nt][2] = b1_s[col]; c1r[nt][3] = b1_s[col + 1];
            }
#pragma unroll
            for (int kt = 0; kt < 4; ++kt)
#pragma unroll
                for (int nt = 0; nt < 16; ++nt) {
                    const int ntg = sub * 16 + nt;
                    uint2 b = *(const uint2*)&w1p[((kt * 32 + ntg) * 32 + lane) * 2];
                    mma_bf16(c1r[nt], A[kt], b.x, b.y);
                }
#pragma unroll
            for (int nt = 0; nt < 16; ++nt) {
                const int ntg = sub * 16 + nt;
                const float p0 = fmaxf(c1r[nt][0], 0.f), p1 = fmaxf(c1r[nt][1], 0.f);
                const float p2 = fmaxf(c1r[nt][2], 0.f), p3 = fmaxf(c1r[nt][3], 0.f);
                h1[r0 * 132 + ntg * 4 + tg]       = pk(p0, p1);
                h1[(r0 + 8) * 132 + ntg * 4 + tg] = pk(p2, p3);
            }
        }
        // h1 is node-pair local: named barrier over the pair's 64 threads
        asm volatile("bar.sync %0, 64;" :: "r"(1 + nloc) : "memory");

        // ---- MLP2: this warp's quarter (4 of 8 n-tiles) ----
        float d[4][4];
#pragma unroll
        for (int nt = 0; nt < 4; ++nt) {
            const int col = (sub * 4 + nt) * 8 + 2 * tg;
            d[nt][0] = b2_s[col]; d[nt][1] = b2_s[col + 1];
            d[nt][2] = b2_s[col]; d[nt][3] = b2_s[col + 1];
        }
#pragma unroll
        for (int kt = 0; kt < 16; ++kt) {
            unsigned a[4];
            a[0] = h1[r0 * 132 + kt * 8 + tg];
            a[1] = h1[(r0 + 8) * 132 + kt * 8 + tg];
            a[2] = h1[r0 * 132 + kt * 8 + 4 + tg];
            a[3] = h1[(r0 + 8) * 132 + kt * 8 + 4 + tg];
#pragma unroll
            for (int nt = 0; nt < 4; ++nt) {
                uint2 b = *(const uint2*)&w2p[((kt * 8 + sub * 4 + nt) * 32 + lane) * 2];
                mma_bf16(d[nt], a, b.x, b.y);
            }
        }

        // ---- epilogue part 1: scaled d -> x2 smem (own rows only) ----
#pragma unroll
        for (int nt = 0; nt < 4; ++nt) {
            const int col = (sub * 4 + nt) * 8 + 2 * tg;
            const float l0 = ls_s[col], l1 = ls_s[col + 1];
            *(float2*)&x2[r0 * X2S + col] =
                make_float2(l0 * d[nt][0], l1 * d[nt][1]);
            *(float2*)&x2[(r0 + 8) * X2S + col] =
                make_float2(l0 * d[nt][2], l1 * d[nt][3]);
        }
        __syncthreads();   // all pairs done writing scaled outputs

        // ---- epilogue part 2: coalesced out = x2 + x (float4) ----
        {
            const float4* xr4 = (const float4*)(x + (size_t)nodebase * TILE);
            float4* o4 = (float4*)(out + (size_t)nodebase * TILE);
#pragma unroll
            for (int i = 0; i < 4; ++i) {
                const int j   = tid + i * 512;       // float4 index in 8-node tile
                const int row = j >> 4;              // 0..127 == x2 row
                const int col = (j & 15) * 4;
                float4 xv = xr4[j];
                const float* xp = &x2[row * X2S + col];
                o4[j] = make_float4(xp[0] + xv.x, xp[1] + xv.y,
                                    xp[2] + xv.z, xp[3] + xv.w);
            }
        }
        __syncthreads();   // protect x2/h1 for next group
    }
}

// =========================================================
extern "C" void kernel_launch(void* const* d_in, const int* in_sizes, int n_in,
                              void* d_out, int out_size)
{
    (void)in_sizes; (void)n_in; (void)out_size;
    const float* x   = (const float*)d_in[0];
    const float* kb  = (const float*)d_in[1];
    const float* fkb = (const float*)d_in[2];
    const int*   ei  = (const int*)  d_in[3];
    const float* kw  = (const float*)d_in[4];
    const float* fkw = (const float*)d_in[5];
    const float* cb  = (const float*)d_in[6];
    const float* lns = (const float*)d_in[7];
    const float* lnb = (const float*)d_in[8];
    const float* w1  = (const float*)d_in[9];
    const float* b1  = (const float*)d_in[10];
    const float* w2  = (const float*)d_in[11];
    const float* b2  = (const float*)d_in[12];
    const float* ls  = (const float*)d_in[13];
    float* out = (float*)d_out;

    const int edge_smem = 57344;   // 56KB: Wp 8K + KBS 16K + XB 32K
    cudaFuncSetAttribute(k_edge, cudaFuncAttributeMaxDynamicSharedMemorySize, edge_smem);
    cudaFuncSetAttribute(k_fuse, cudaFuncAttributeMaxDynamicSharedMemorySize, FUSE_SMEM_BYTES);

    k_prep0<<<2560, 256>>>(x);
    k_fk<<<OO * OO, 32>>>(fkb, fkw);
    k_pack<<<16, 256>>>(kw, w1, w2);
    k_edge<<<EE / 32, 256, edge_smem>>>(kb, ei);
    k_fuse<<<148, 512, FUSE_SMEM_BYTES>>>(x, cb, lns, lnb, b1, b2, ls, out);
}

// round 17
// speedup vs baseline: 1.0099x; 1.0099x over previous
#include <cuda_runtime.h>
#include <cuda_bf16.h>

#define NN   10000
#define OO   16
#define CC   64
#define EE   100000
#define KDD  64
#define NOC  (NN*OO*CC)          // 10,240,000
#define TILE (OO*CC)             // 1024 elements per node/edge tile
#define NGRP (NN/8)              // 1250 groups of 8 nodes

// column permutation applied to g_x1 / g_xb tiles (element index within a 64-elem row)
// (row&7)<<3: 32-bank-conflict-free fragment access in k_edge msg hmul, while
// preserving 8-element (16B) block alignment for vector ld/st.
#define PERM(row, col) ((col) ^ (((row) & 7) << 3))

// -------- device scratch (no allocations allowed) --------
__device__ __align__(16) __nv_bfloat16  g_x1[NOC];      // 20.5 MB spatial-conv accumulator (bf16, PERMuted)
__device__ __align__(16) __nv_bfloat16  g_xb[NOC];      // 20.5 MB bf16 permuted copy of x
__device__ __align__(16) __nv_bfloat162 g_fkb[8192];    // fiber kernel bf16 (pre /O)
__device__ __align__(16) unsigned       g_kwp[2048];    // kernel_w  B-frags (4kt x 8nt)
__device__ __align__(16) unsigned       g_w1p[8192];    // w1 B-frags (4kt x 32nt)
__device__ __align__(16) unsigned       g_w2p[8192];    // w2 B-frags (16kt x 8nt)

// -------- helpers --------
__device__ __forceinline__ unsigned pk(float lo, float hi) {
    __nv_bfloat162 t = __floats2bfloat162_rn(lo, hi);   // .x = lo (low 16 bits)
    return *reinterpret_cast<unsigned*>(&t);
}

__device__ __forceinline__ void mma_bf16(float* c, const unsigned* a, unsigned b0, unsigned b1) {
    asm volatile(
        "mma.sync.aligned.m16n8k16.row.col.f32.bf16.bf16.f32 "
        "{%0,%1,%2,%3}, {%4,%5,%6,%7}, {%8,%9}, {%0,%1,%2,%3};"
        : "+f"(c[0]), "+f"(c[1]), "+f"(c[2]), "+f"(c[3])
        : "r"(a[0]), "r"(a[1]), "r"(a[2]), "r"(a[3]), "r"(b0), "r"(b1));
}

__device__ __forceinline__ void mbar_wait(unsigned mbar, int phase) {
    asm volatile(
        "{\n\t.reg .pred P1;\n\t"
        "WAIT_LOOP_%=:\n\t"
        "mbarrier.try_wait.parity.acquire.cta.shared::cta.b64 P1, [%0], %1, 0x989680;\n\t"
        "@P1 bra.uni WAIT_DONE_%=;\n\t"
        "bra.uni WAIT_LOOP_%=;\n\t"
        "WAIT_DONE_%=:\n\t}"
        :: "r"(mbar), "r"(phase) : "memory");
}

// =========================================================
// K0: fused prep — zero g_x1 AND build g_xb (bf16 permuted x) in one pass
// =========================================================
__global__ void k_prep0(const float* __restrict__ x) {
    const int n4 = NOC / 4;          // 2,560,000 float4s
    int i = blockIdx.x * blockDim.x + threadIdx.x;
    const int stride = gridDim.x * blockDim.x;
    const uint2 z = make_uint2(0u, 0u);
    for (; i < n4; i += stride) {
        float4 v = ((const float4*)x)[i];
        const int node = i >> 8;
        const int f    = (i & 255) * 4;      // element index within tile
        const int row  = f >> 6, col = f & 63;
        const int pc   = PERM(row, col);
        uint2 o;
        o.x = pk(v.x, v.y);
        o.y = pk(v.z, v.w);
        *(uint2*)(g_xb + (size_t)node * 1024 + row * 64 + pc) = o;
        *(uint2*)(g_x1 + (size_t)node * 1024 + row * 64 + pc) = z;
    }
}

// =========================================================
// K1: fk[p][o][c] = (1/O) * sum_kd FKB[p,o,kd] * FW[kd,c]  -> bf16 pairs
// =========================================================
__global__ void k_fk(const float* __restrict__ fkb, const float* __restrict__ fw) {
    __shared__ float s[KDD];
    const int po = blockIdx.x;
    const int t  = threadIdx.x;
    s[t]      = fkb[po * KDD + t];
    s[t + 32] = fkb[po * KDD + t + 32];
    __syncthreads();
    float a0 = 0.f, a1 = 0.f;
#pragma unroll 16
    for (int kd = 0; kd < KDD; kd++) {
        a0 += s[kd] * fw[kd * CC + 2 * t];
        a1 += s[kd] * fw[kd * CC + 2 * t + 1];
    }
    g_fkb[po * 32 + t] = __floats2bfloat162_rn(a0 * (1.0f / OO), a1 * (1.0f / OO));
}

// =========================================================
// K1b: pack kernel_w / w1 / w2 into mma B-fragment layout (bf16)
// Parallelized over 16 blocks x 8 warps = 128 warp-slots.
// =========================================================
__global__ void k_pack(const float* __restrict__ kw,
                       const float* __restrict__ w1,
                       const float* __restrict__ w2) {
    const int tid  = threadIdx.x;
    const int wrp  = tid >> 5, lane = tid & 31;
    const int g    = lane >> 2, tg = lane & 3;
    const int slot = blockIdx.x * 8 + wrp;      // 0..127
    for (int f = slot; f < 32; f += 128) {
        const int kt = f >> 3, nt = f & 7;
        const int k = kt * 16 + 2 * tg, n = nt * 8 + g;
        g_kwp[(f * 32 + lane) * 2 + 0] = pk(kw[k * 64 + n],       kw[(k + 1) * 64 + n]);
        g_kwp[(f * 32 + lane) * 2 + 1] = pk(kw[(k + 8) * 64 + n], kw[(k + 9) * 64 + n]);
    }
    for (int f = slot; f < 128; f += 128) {
        const int kt = f >> 5, nt = f & 31;
        const int k = kt * 16 + 2 * tg, n = nt * 8 + g;
        g_w1p[(f * 32 + lane) * 2 + 0] = pk(w1[k * 256 + n],       w1[(k + 1) * 256 + n]);
        g_w1p[(f * 32 + lane) * 2 + 1] = pk(w1[(k + 8) * 256 + n], w1[(k + 9) * 256 + n]);
    }
    for (int f = slot; f < 128; f += 128) {
        const int kt = f >> 3, nt = f & 7;
        const int k = kt * 16 + 2 * tg, n = nt * 8 + g;
        g_w2p[(f * 32 + lane) * 2 + 0] = pk(w2[k * 64 + n],       w2[(k + 1) * 64 + n]);
        g_w2p[(f * 32 + lane) * 2 + 1] = pk(w2[(k + 8) * 64 + n], w2[(k + 9) * 64 + n]);
    }
}

// =========================================================
// K2: edge conv, software-pipelined: edge e+1's kb LDGs are issued right
// after edge e's kv registers are consumed (converted to bf16 smem), so
// the kb DRAM latency hides behind a full edge's mma+scatter work.
// kb streamed with L2::evict_first; x from bf16 g_xb; msg built in-place
// in a double-buffered bf16 scatter buffer (conflict-free via PERM).
// 8 warps/block, 4 edges/warp, grid=3125.
// smem: Wp 8KB + KBS 16KB + XB 32KB = 56KB, 3 blocks/SM.
// =========================================================
__global__ void __launch_bounds__(256, 3) k_edge(
    const float* __restrict__ kb,
    const int*   __restrict__ ei)
{
    extern __shared__ float sme[];
    unsigned* Wp      = (unsigned*)sme;             // 2048 u32  (8KB)
    unsigned* KBS_all = Wp + 2048;                  // 4096 u32  (16KB) bf16 kb tiles
    unsigned* XB_all  = KBS_all + 4096;             // 8 warps x 2 x 512 u32 (32KB)

    const int tid  = threadIdx.x;
    const int wrp  = tid >> 5, lane = tid & 31;
    const int g    = lane >> 2, tg = lane & 3;

    for (int i = tid; i < 2048; i += 256) Wp[i] = g_kwp[i];
    __syncthreads();

    char*     KBS = (char*)(KBS_all + wrp * 512);   // 2KB bf16 tile, swizzled
    unsigned* XB  = XB_all + wrp * 1024;            // 2 x 2KB bf16 msg buffers

    // L2 eviction policy: kb is streamed once, keep xb/x1 resident
    unsigned long long pol;
    asm volatile("createpolicy.fractional.L2::evict_first.b64 %0, 1.0;" : "=l"(pol));

    const int lrow  = lane & 15;
    const int lhalf = lane >> 4;
    const unsigned kbs_base = (unsigned)__cvta_generic_to_shared(KBS);
    const int ebase = blockIdx.x * 32 + wrp * 4;

    // ---- prologue: issue edge 0's kb loads ----
    float4 kv[8];
    {
        const float4* kb4 = (const float4*)(kb + (size_t)ebase * TILE);
#pragma unroll
        for (int i = 0; i < 8; ++i)
            asm volatile("ld.global.nc.L2::cache_hint.v4.f32 {%0,%1,%2,%3}, [%4], %5;"
                         : "=f"(kv[i].x), "=f"(kv[i].y), "=f"(kv[i].z), "=f"(kv[i].w)
                         : "l"(kb4 + i * 32 + lane), "l"(pol));
    }

#pragma unroll 1
    for (int it = 0; it < 4; ++it) {
        const int e   = ebase + it;
        const int src = ei[e];
        const int dst = ei[EE + e];

        const int buf = it & 1;
        unsigned* mb = XB + buf * 512;
        // drain scatter that used this buffer (issued 2 iterations ago)
        if (lane == 0 && it >= 2)
            asm volatile("cp.async.bulk.wait_group 1;" ::: "memory");
        __syncwarp();

        // ---- convert current kv (edge it's kb) -> bf16 swizzled smem ----
#pragma unroll
        for (int i = 0; i < 8; ++i) {
            const int idx = i * 32 + lane;          // float4 index in tile
            const int row = idx >> 4;               // 0..15
            const int bc  = (idx & 15) * 8;         // byte col (0..120)
            const int bcs = bc ^ ((row & 7) << 4);  // SW128 swizzle
            uint2 v;
            v.x = pk(kv[i].x, kv[i].y);
            v.y = pk(kv[i].z, kv[i].w);
            *(uint2*)(KBS + row * 128 + bcs) = v;
        }

        // ---- issue NEXT edge's kb loads into the freed kv registers ----
        if (it < 3) {
            const float4* kbn = (const float4*)(kb + (size_t)(e + 1) * TILE);
#pragma unroll
            for (int i = 0; i < 8; ++i)
                asm volatile("ld.global.nc.L2::cache_hint.v4.f32 {%0,%1,%2,%3}, [%4], %5;"
                             : "=f"(kv[i].x), "=f"(kv[i].y), "=f"(kv[i].z), "=f"(kv[i].w)
                             : "l"(kbn + i * 32 + lane), "l"(pol));
        }

        // ---- xb (already permuted bf16) -> msg buffer, 2 chunks of 2 uint4 ----
        const uint4* xb4 = (const uint4*)(g_xb + (size_t)src * TILE);
#pragma unroll
        for (int ch = 0; ch < 2; ++ch) {
            uint4 xv[2];
#pragma unroll
            for (int i = 0; i < 2; ++i) xv[i] = xb4[(ch * 2 + i) * 32 + lane];
#pragma unroll
            for (int i = 0; i < 2; ++i) ((uint4*)mb)[(ch * 2 + i) * 32 + lane] = xv[i];
        }
        __syncwarp();   // KBS + mb staging visible warp-wide

        // ---- A fragments via ldmatrix ----
        unsigned A[4][4];
#pragma unroll
        for (int kt = 0; kt < 4; ++kt) {
            const int bc  = kt * 32 + lhalf * 16;
            const unsigned addr = kbs_base + lrow * 128 + (bc ^ ((lrow & 7) << 4));
            asm volatile(
                "ldmatrix.sync.aligned.m8n8.x4.shared.b16 {%0,%1,%2,%3}, [%4];"
                : "=r"(A[kt][0]), "=r"(A[kt][1]), "=r"(A[kt][2]), "=r"(A[kt][3])
                : "r"(addr));
        }

        // ---- 2 passes of 4 n-tiles: mma then in-place msg hmul ----
#pragma unroll 1
        for (int pass = 0; pass < 2; ++pass) {
            float c[4][4];
#pragma unroll
            for (int ntl = 0; ntl < 4; ++ntl)
                c[ntl][0] = c[ntl][1] = c[ntl][2] = c[ntl][3] = 0.f;
#pragma unroll
            for (int kt = 0; kt < 4; ++kt)
#pragma unroll
                for (int ntl = 0; ntl < 4; ++ntl) {
                    const int nt = pass * 4 + ntl;
                    uint2 b = *(const uint2*)&Wp[((kt * 8 + nt) * 32 + lane) * 2];
                    mma_bf16(c[ntl], A[kt], b.x, b.y);
                }
#pragma unroll
            for (int ntl = 0; ntl < 4; ++ntl) {
                const int nt = pass * 4 + ntl;
                const int c0 = nt * 8 + 2 * tg;
                const int w  = PERM(g, c0) >> 1;    // bf162 word col (same for g, g+8)
                unsigned x0 = mb[g * 32 + w];
                unsigned x1 = mb[(g + 8) * 32 + w];
                unsigned k0 = pk(c[ntl][0], c[ntl][1]);
                unsigned k1 = pk(c[ntl][2], c[ntl][3]);
                __nv_bfloat162 m0 = __hmul2(*(__nv_bfloat162*)&x0, *(__nv_bfloat162*)&k0);
                __nv_bfloat162 m1 = __hmul2(*(__nv_bfloat162*)&x1, *(__nv_bfloat162*)&k1);
                mb[g * 32 + w]       = *(unsigned*)&m0;
                mb[(g + 8) * 32 + w] = *(unsigned*)&m1;
            }
        }
        __syncwarp();

        if (lane == 0) {
            asm volatile("fence.proxy.async.shared::cta;" ::: "memory");
            unsigned saddr = (unsigned)__cvta_generic_to_shared(mb);
            char* gptr = (char*)g_x1 + (size_t)dst * 2048;
            asm volatile(
                "cp.reduce.async.bulk.global.shared::cta.bulk_group.add.noftz.bf16 [%0], [%1], %2;"
                :: "l"(gptr), "r"(saddr), "r"(2048) : "memory");
            asm volatile("cp.async.bulk.commit_group;" ::: "memory");
        }
    }
    if (lane == 0)
        asm volatile("cp.async.bulk.wait_group 0;" ::: "memory");
    __syncwarp();
}

// =========================================================
// K3: persistent fused fiber conv + LN + bf16-MMA MLP + residual
// grid=148, 512 threads. x1 tiles prefetched via cp.async.bulk (double buffer),
// fk in registers, per-node-pair named barrier between MLP1/MLP2,
// epilogue staged through x2 smem for fully coalesced residual+store.
// =========================================================
#define X2S 68                                 // x2 row stride (float4-aligned)
#define FUSE_SMEM_FLOATS (8192*2 + 128*X2S + 128 + 128 + 256 + 64*5 + 4 + 16896 + 8192)
#define FUSE_SMEM_BYTES  (FUSE_SMEM_FLOATS * 4)

__global__ void __launch_bounds__(512, 1) k_fuse(
    const float* __restrict__ x,
    const float* __restrict__ cb,
    const float* __restrict__ lns,
    const float* __restrict__ lnb,
    const float* __restrict__ b1,
    const float* __restrict__ b2,
    const float* __restrict__ ls,
    float*       __restrict__ out)
{
    extern __shared__ float sm[];
    unsigned* w1p  = (unsigned*)sm;                    // 8192 u32 (32KB)
    unsigned* w2p  = w1p + 8192;                       // 8192 u32 (32KB)
    float* x2    = (float*)(w2p + 8192);               // 128 x 68 f32 (34.8KB)
    float* mu_s  = x2 + 128 * X2S;                     // 128
    float* rs_s  = mu_s + 128;                         // 128
    float* b1_s  = rs_s + 128;                         // 256
    float* b2_s  = b1_s + 256;                         // 64
    float* ls_s  = b2_s + 64;                          // 64
    float* lns_s = ls_s + 64;                          // 64
    float* lnb_s = lns_s + 64;                         // 64
    float* cb_s  = lnb_s + 64;                         // 64
    unsigned long long* mbar = (unsigned long long*)(cb_s + 64);  // 2 mbarriers (16B)
    unsigned* h1 = (unsigned*)(mbar + 2);              // 128 x 132 u32 (66KB)
    __nv_bfloat16* stage = (__nv_bfloat16*)(h1 + 16896); // 2 x 8192 bf16 (32KB)

    const int tid  = threadIdx.x;
    const int wrp  = tid >> 5, lane = tid & 31;
    const int g    = lane >> 2, tg = lane & 3;
    const int nloc = wrp >> 1;        // 0..7: node within group
    const int sub  = wrp & 1;         // warp's half of the MLP

    const unsigned mb0 = (unsigned)__cvta_generic_to_shared(&mbar[0]);
    const unsigned mb1 = (unsigned)__cvta_generic_to_shared(&mbar[1]);

    for (int i = tid; i < 8192; i += 512) {
        w1p[i] = g_w1p[i];
        w2p[i] = g_w2p[i];
    }
    if (tid < 64) {
        b2_s[tid]  = b2[tid];
        ls_s[tid]  = ls[tid] * 1e-6f;   // fold LS_VAL
        lns_s[tid] = lns[tid];
        lnb_s[tid] = lnb[tid];
        cb_s[tid]  = cb[tid];
    }
    if (tid < 256) b1_s[tid] = b1[tid];
    if (tid == 0) {
        asm volatile("mbarrier.init.shared.b64 [%0], 1;" :: "r"(mb0) : "memory");
        asm volatile("mbarrier.init.shared.b64 [%0], 1;" :: "r"(mb1) : "memory");
    }

    // ---- hoist fiber kernel into registers: thread = (c4, p, half) ----
    const int c4 = tid & 15, fp_ = (tid >> 4) & 15, half = tid >> 8;
    __nv_bfloat162 fkr0[16], fkr1[16];
#pragma unroll
    for (int o = 0; o < 16; ++o) {
        uint2 v = *(const uint2*)&((const unsigned*)g_fkb)[fp_ * 512 + o * 32 + 2 * c4];
        fkr0[o] = *reinterpret_cast<__nv_bfloat162*>(&v.x);
        fkr1[o] = *reinterpret_cast<__nv_bfloat162*>(&v.y);
    }
    __syncthreads();
    const float4 cbv = *(const float4*)&cb_s[4 * c4];

    // ---- prologue: prefetch first group's x1 tile into stage buf 0 ----
    if (tid == 0) {
        asm volatile("mbarrier.arrive.expect_tx.shared.b64 _, [%0], 16384;" :: "r"(mb0) : "memory");
        unsigned sdst = (unsigned)__cvta_generic_to_shared(stage);
        const char* gsrc = (const char*)g_x1 + (size_t)blockIdx.x * 16384;
        asm volatile(
            "cp.async.bulk.shared::cta.global.mbarrier::complete_tx::bytes [%0], [%1], 16384, [%2];"
            :: "r"(sdst), "l"(gsrc), "r"(mb0) : "memory");
    }

    int ph0 = 0, ph1 = 0;
    int it = 0;
#pragma unroll 1
    for (int grp = blockIdx.x; grp < NGRP; grp += 148, ++it) {
        const int nodebase = grp * 8;
        const int buf = it & 1;
        const __nv_bfloat16* stg = stage + buf * 8192;

        // ---- wait for this group's x1 tile ----
        if (buf == 0) { mbar_wait(mb0, ph0); ph0 ^= 1; }
        else          { mbar_wait(mb1, ph1); ph1 ^= 1; }

        // ---- fiber conv (bf162 hfma2, fk in regs): 4 nodes per thread ----
#pragma unroll
        for (int n = 0; n < 4; ++n) {
            const int node = half * 4 + n;
            const __nv_bfloat16* sp = stg + node * 1024;
            __nv_bfloat162 acc0 = __floats2bfloat162_rn(0.f, 0.f);
            __nv_bfloat162 acc1 = acc0;
#pragma unroll
            for (int o = 0; o < 16; ++o) {
                uint2 xv = *(const uint2*)(sp + o * 64 + PERM(o, 4 * c4));
                acc0 = __hfma2(*reinterpret_cast<__nv_bfloat162*>(&xv.x), fkr0[o], acc0);
                acc1 = __hfma2(*reinterpret_cast<__nv_bfloat162*>(&xv.y), fkr1[o], acc1);
            }
            float2 a0 = __bfloat1622float2(acc0);
            float2 a1 = __bfloat1622float2(acc1);
            *(float4*)&x2[(node * 16 + fp_) * X2S + 4 * c4] =
                make_float4(a0.x + cbv.x, a0.y + cbv.y, a1.x + cbv.z, a1.y + cbv.w);
        }
        __syncthreads();   // x2 ready; everyone done reading stage[buf]

        // ---- prefetch next group's x1 into the other buffer ----
        if (tid == 0 && grp + 148 < NGRP) {
            const unsigned mbn = (buf == 0) ? mb1 : mb0;
            asm volatile("mbarrier.arrive.expect_tx.shared.b64 _, [%0], 16384;" :: "r"(mbn) : "memory");
            unsigned sdst = (unsigned)__cvta_generic_to_shared(stage + (buf ^ 1) * 8192);
            const char* gsrc = (const char*)g_x1 + (size_t)(grp + 148) * 16384;
            asm volatile(
                "cp.async.bulk.shared::cta.global.mbarrier::complete_tx::bytes [%0], [%1], 16384, [%2];"
                :: "r"(sdst), "l"(gsrc), "r"(mbn) : "memory");
        }

        // ---- LayerNorm stats: 4 threads per row (float4, aligned via X2S=68) ----
        {
            const int row = tid >> 2, q = tid & 3;
            const float* xr = x2 + row * X2S + q * 16;
            float s = 0.f, ss = 0.f;
#pragma unroll
            for (int j = 0; j < 4; ++j) {
                float4 v = *(const float4*)(xr + j * 4);
                s  += v.x + v.y + v.z + v.w;
                ss += v.x * v.x + v.y * v.y + v.z * v.z + v.w * v.w;
            }
            s  += __shfl_xor_sync(0xffffffffu, s, 1);
            ss += __shfl_xor_sync(0xffffffffu, ss, 1);
            s  += __shfl_xor_sync(0xffffffffu, s, 2);
            ss += __shfl_xor_sync(0xffffffffu, ss, 2);
            if (q == 0) {
                const float mu  = s * (1.f / 64.f);
                const float var = ss * (1.f / 64.f) - mu * mu;
                mu_s[row] = mu;
                rs_s[row] = rsqrtf(var + 1e-6f);
            }
        }
        __syncthreads();

        // ---- build normalized A fragments ----
        const int r0  = nloc * 16 + g;
        const float mu0 = mu_s[r0],     rs0 = rs_s[r0];
        const float mu1 = mu_s[r0 + 8], rs1 = rs_s[r0 + 8];
        unsigned A[4][4];
#pragma unroll
        for (int kt = 0; kt < 4; ++kt) {
            const int k0 = kt * 16 + 2 * tg;
            float2 sc0 = *(float2*)(lns_s + k0),     bi0 = *(float2*)(lnb_s + k0);
            float2 sc1 = *(float2*)(lns_s + k0 + 8), bi1 = *(float2*)(lnb_s + k0 + 8);
            float2 v;
            v = *(float2*)(x2 + r0 * X2S + k0);
            A[kt][0] = pk((v.x - mu0) * rs0 * sc0.x + bi0.x, (v.y - mu0) * rs0 * sc0.y + bi0.y);
            v = *(float2*)(x2 + (r0 + 8) * X2S + k0);
            A[kt][1] = pk((v.x - mu1) * rs1 * sc0.x + bi0.x, (v.y - mu1) * rs1 * sc0.y + bi0.y);
            v = *(float2*)(x2 + r0 * X2S + k0 + 8);
            A[kt][2] = pk((v.x - mu0) * rs0 * sc1.x + bi1.x, (v.y - mu0) * rs0 * sc1.y + bi1.y);
            v = *(float2*)(x2 + (r0 + 8) * X2S + k0 + 8);
            A[kt][3] = pk((v.x - mu1) * rs1 * sc1.x + bi1.x, (v.y - mu1) * rs1 * sc1.y + bi1.y);
        }

        // ---- MLP1: this warp's half (16 of 32 n-tiles) ----
        {
            float c1r[16][4];
#pragma unroll
            for (int nt = 0; nt < 16; ++nt) {
                const int col = (sub * 16 + nt) * 8 + 2 * tg;
                c1r[nt][0] = b1_s[col]; c1r[nt][1] = b1_s[col + 1];
                c1r[nt][2] = b1_s[col]; c1r[nt][3] = b1_s[col + 1];
            }
#pragma unroll
            for (int kt = 0; kt < 4; ++kt)
#pragma unroll
                for (int nt = 0; nt < 16; ++nt) {
                    const int ntg = sub * 16 + nt;
                    uint2 b = *(const uint2*)&w1p[((kt * 32 + ntg) * 32 + lane) * 2];
                    mma_bf16(c1r[nt], A[kt], b.x, b.y);
                }
#pragma unroll
            for (int nt = 0; nt < 16; ++nt) {
                const int ntg = sub * 16 + nt;
                const float p0 = fmaxf(c1r[nt][0], 0.f), p1 = fmaxf(c1r[nt][1], 0.f);
                const float p2 = fmaxf(c1r[nt][2], 0.f), p3 = fmaxf(c1r[nt][3], 0.f);
                h1[r0 * 132 + ntg * 4 + tg]       = pk(p0, p1);
                h1[(r0 + 8) * 132 + ntg * 4 + tg] = pk(p2, p3);
            }
        }
        // h1 is node-pair local: named barrier over the pair's 64 threads
        asm volatile("bar.sync %0, 64;" :: "r"(1 + nloc) : "memory");

        // ---- MLP2: this warp's quarter (4 of 8 n-tiles) ----
        float d[4][4];
#pragma unroll
        for (int nt = 0; nt < 4; ++nt) {
            const int col = (sub * 4 + nt) * 8 + 2 * tg;
            d[nt][0] = b2_s[col]; d[nt][1] = b2_s[col + 1];
            d[nt][2] = b2_s[col]; d[nt][3] = b2_s[col + 1];
        }
#pragma unroll
        for (int kt = 0; kt < 16; ++kt) {
            unsigned a[4];
            a[0] = h1[r0 * 132 + kt * 8 + tg];
            a[1] = h1[(r0 + 8) * 132 + kt * 8 + tg];
            a[2] = h1[r0 * 132 + kt * 8 + 4 + tg];
            a[3] = h1[(r0 + 8) * 132 + kt * 8 + 4 + tg];
#pragma unroll
            for (int nt = 0; nt < 4; ++nt) {
                uint2 b = *(const uint2*)&w2p[((kt * 8 + sub * 4 + nt) * 32 + lane) * 2];
                mma_bf16(d[nt], a, b.x, b.y);
            }
        }

        // ---- epilogue part 1: scaled d -> x2 smem (own rows only) ----
#pragma unroll
        for (int nt = 0; nt < 4; ++nt) {
            const int col = (sub * 4 + nt) * 8 + 2 * tg;
            const float l0 = ls_s[col], l1 = ls_s[col + 1];
            *(float2*)&x2[r0 * X2S + col] =
                make_float2(l0 * d[nt][0], l1 * d[nt][1]);
            *(float2*)&x2[(r0 + 8) * X2S + col] =
                make_float2(l0 * d[nt][2], l1 * d[nt][3]);
        }
        __syncthreads();   // all pairs done writing scaled outputs

        // ---- epilogue part 2: coalesced out = x2 + x (float4) ----
        {
            const float4* xr4 = (const float4*)(x + (size_t)nodebase * TILE);
            float4* o4 = (float4*)(out + (size_t)nodebase * TILE);
#pragma unroll
            for (int i = 0; i < 4; ++i) {
                const int j   = tid + i * 512;       // float4 index in 8-node tile
                const int row = j >> 4;              // 0..127 == x2 row
                const int col = (j & 15) * 4;
                float4 xv = xr4[j];
                const float* xp = &x2[row * X2S + col];
                o4[j] = make_float4(xp[0] + xv.x, xp[1] + xv.y,
                                    xp[2] + xv.z, xp[3] + xv.w);
            }
        }
        __syncthreads();   // protect x2/h1 for next group
    }
}

// =========================================================
extern "C" void kernel_launch(void* const* d_in, const int* in_sizes, int n_in,
                              void* d_out, int out_size)
{
    (void)in_sizes; (void)n_in; (void)out_size;
    const float* x   = (const float*)d_in[0];
    const float* kb  = (const float*)d_in[1];
    const float* fkb = (const float*)d_in[2];
    const int*   ei  = (const int*)  d_in[3];
    const float* kw  = (const float*)d_in[4];
    const float* fkw = (const float*)d_in[5];
    const float* cb  = (const float*)d_in[6];
    const float* lns = (const float*)d_in[7];
    const float* lnb = (const float*)d_in[8];
    const float* w1  = (const float*)d_in[9];
    const float* b1  = (const float*)d_in[10];
    const float* w2  = (const float*)d_in[11];
    const float* b2  = (const float*)d_in[12];
    const float* ls  = (const float*)d_in[13];
    float* out = (float*)d_out;

    const int edge_smem = 57344;   // 56KB: Wp 8K + KBS 16K + XB 32K
    cudaFuncSetAttribute(k_edge, cudaFuncAttributeMaxDynamicSharedMemorySize, edge_smem);
    cudaFuncSetAttribute(k_fuse, cudaFuncAttributeMaxDynamicSharedMemorySize, FUSE_SMEM_BYTES);

    k_prep0<<<2560, 256>>>(x);
    k_fk<<<OO * OO, 32>>>(fkb, fkw);
    k_pack<<<16, 256>>>(kw, w1, w2);
    k_edge<<<EE / 32, 256, edge_smem>>>(kb, ei);
    k_fuse<<<148, 512, FUSE_SMEM_BYTES>>>(x, cb, lns, lnb, b1, b2, ls, out);
}